// round 2
// baseline (speedup 1.0000x reference)
#include <cuda_runtime.h>
#include <cstddef>

// Problem constants
#define NB   16
#define NT   64
#define NF0  8
#define NN   100
#define BT   (NB * NT)            // 1024
#define ROWSTRIDE (NF0 * NN)      // 800 floats per (b,t) slice
#define SLAB ((size_t)BT * ROWSTRIDE)  // 819200 floats per k-slab

// Diffusion scratch: z_k for k = 1..15  (k=0 is just x, read directly)
__device__ float g_z[15 * BT * ROWSTRIDE];   // ~49.15 MB

// ---------------------------------------------------------------------------
// Diffusion step: z_k[b,t] = z_{k-1}[b,t-1] @ S[b,t]   (zero for t < k)
// One block per (b,t). A=[8,100] in smem, S streamed as float4 from L2.
// Thread tile: 2 f-rows x 4 m-cols -> 0.25 LDS/FMA.
// ---------------------------------------------------------------------------
__global__ __launch_bounds__(128)
void diffuse_step_kernel(const float* __restrict__ x,
                         const float* __restrict__ S,
                         int k)
{
    int bt  = blockIdx.x;          // b*64 + t
    int t   = bt & 63;
    int tid = threadIdx.x;
    float* dst = g_z + (size_t)(k - 1) * SLAB + (size_t)bt * ROWSTRIDE;

    if (t < k) {                   // chain runs off the front -> exact zero
        for (int i = tid; i < ROWSTRIDE; i += 128) dst[i] = 0.f;
        return;
    }

    const float* src = (k == 1)
        ? (x + (size_t)(bt - 1) * ROWSTRIDE)
        : (g_z + (size_t)(k - 2) * SLAB + (size_t)(bt - 1) * ROWSTRIDE);

    __shared__ float Ash[ROWSTRIDE];
    for (int i = tid; i < ROWSTRIDE; i += 128) Ash[i] = src[i];
    __syncthreads();

    if (tid < 100) {
        int mg = tid % 25;             // 25 m-quads
        int fg = tid / 25;             // 4 f-pairs
        int m0 = mg * 4;
        const float* A0 = Ash + (fg * 2) * NN;
        const float* A1 = A0 + NN;
        const float* Sp = S + (size_t)bt * (NN * NN) + m0;

        float a00 = 0.f, a01 = 0.f, a02 = 0.f, a03 = 0.f;
        float a10 = 0.f, a11 = 0.f, a12 = 0.f, a13 = 0.f;
        #pragma unroll 4
        for (int n = 0; n < NN; n++) {
            float4 s = *reinterpret_cast<const float4*>(Sp + (size_t)n * NN);
            float va = A0[n], vb = A1[n];
            a00 = fmaf(va, s.x, a00); a01 = fmaf(va, s.y, a01);
            a02 = fmaf(va, s.z, a02); a03 = fmaf(va, s.w, a03);
            a10 = fmaf(vb, s.x, a10); a11 = fmaf(vb, s.y, a11);
            a12 = fmaf(vb, s.z, a12); a13 = fmaf(vb, s.w, a13);
        }
        float* d0 = dst + (fg * 2) * NN + m0;
        float* d1 = d0 + NN;
        d0[0] = a00; d0[1] = a01; d0[2] = a02; d0[3] = a03;
        d1[0] = a10; d1[1] = a11; d1[2] = a12; d1[3] = a13;
    }
}

// ---------------------------------------------------------------------------
// Fused head: gather z row [8][16] -> conv1(K=4)+relu+pool2 -> [32][6]
//             -> conv2(K=3)+relu+pool2 -> [64][2] -> fc1(128->64)+relu
//             -> fc2(64->5) -> out[b,t,o,n]
// 32 rows per block, 256 threads. Shared buffers stage-overlaid.
// ---------------------------------------------------------------------------
#define ZS   129
#define Y1S  193
#define Y2S  129
#define HS   65
#define OFF_HSH 4128
#define OFF_Y1  6208
#define OFF_W1  12384
#define OFF_B1  13408
#define OFF_W2  13440
#define SMEM_FLOATS 22085

__global__ __launch_bounds__(256, 2)
void head_kernel(const float* __restrict__ x,
                 const float* __restrict__ w1g, const float* __restrict__ b1g,
                 const float* __restrict__ w2g, const float* __restrict__ b2g,
                 const float* __restrict__ f1wg, const float* __restrict__ f1bg,
                 const float* __restrict__ f2wg, const float* __restrict__ f2bg,
                 float* __restrict__ out)
{
    extern __shared__ float sm[];
    float* zsh  = sm;
    float* y2sh = sm;                 // reuses zsh region after conv1
    float* hsh  = sm + OFF_HSH;
    float* y1sh = sm + OFF_Y1;
    float* w1sh = sm + OFF_W1;
    float* b1sh = sm + OFF_B1;

    int tid  = threadIdx.x;
    int row0 = blockIdx.x * 32;       // global row = (b*T + t)*N + n

    // ---- stage 0: gather z tile (32 rows x 8 f x 16 k = 4096) + weights ----
    for (int i = tid; i < 4096; i += 256) {
        int r  = i & 31;
        int kf = i >> 5;              // 0..127
        int f  = kf >> 4;             // 0..7
        int k  = kf & 15;             // 0..15
        int R  = row0 + r;
        int n  = R % NN;
        int bt = R / NN;
        const float* srcp = (k == 0) ? x : (g_z + (size_t)(k - 1) * SLAB);
        zsh[r * ZS + f * 16 + k] = srcp[(size_t)bt * ROWSTRIDE + f * NN + n];
    }
    for (int i = tid; i < 1024; i += 256) w1sh[i] = w1g[i];
    if (tid < 32) b1sh[tid] = b1g[tid];
    {
        float* w2sh = sm + OFF_W2;
        for (int i = tid; i < 6144; i += 256) w2sh[i] = w2g[i];
        if (tid < 64) w2sh[6144 + tid] = b2g[tid];
    }
    __syncthreads();

    // ---- conv1 + relu + maxpool2 : thread = (r, 4 channels) ----
    {
        int r = tid & 31, fg = tid >> 5;       // fg in [0,8): channels fg*4..+3
        float acc[4][12];
        #pragma unroll
        for (int c = 0; c < 4; c++)
            #pragma unroll
            for (int l = 0; l < 12; l++) acc[c][l] = 0.f;

        #pragma unroll 2
        for (int f0 = 0; f0 < 8; f0++) {
            float a[16];
            #pragma unroll
            for (int i = 0; i < 16; i++) a[i] = zsh[r * ZS + f0 * 16 + i];
            #pragma unroll
            for (int kk = 0; kk < 4; kk++) {
                #pragma unroll
                for (int c = 0; c < 4; c++) {
                    float w = w1sh[(fg * 4 + c) * 32 + f0 * 4 + kk];
                    #pragma unroll
                    for (int l = 0; l < 12; l++)
                        acc[c][l] = fmaf(a[l + kk], w, acc[c][l]);
                }
            }
        }
        #pragma unroll
        for (int c = 0; c < 4; c++) {
            int f1 = fg * 4 + c;
            float bb = b1sh[f1];
            #pragma unroll
            for (int lp = 0; lp < 6; lp++) {
                float v0 = fmaxf(acc[c][2 * lp]     + bb, 0.f);
                float v1 = fmaxf(acc[c][2 * lp + 1] + bb, 0.f);
                y1sh[r * Y1S + f1 * 6 + lp] = fmaxf(v0, v1);
            }
        }
    }
    __syncthreads();

    // ---- conv2 + relu + maxpool2 : thread = (r, 8 channels) ----
    {
        const float* w2sh = sm + OFF_W2;
        const float* b2sh = w2sh + 6144;
        int r = tid & 31, fg = tid >> 5;       // channels fg*8..+7
        float acc[8][4];
        #pragma unroll
        for (int c = 0; c < 8; c++)
            #pragma unroll
            for (int l = 0; l < 4; l++) acc[c][l] = 0.f;

        #pragma unroll 4
        for (int f1 = 0; f1 < 32; f1++) {
            float a[6];
            #pragma unroll
            for (int i = 0; i < 6; i++) a[i] = y1sh[r * Y1S + f1 * 6 + i];
            #pragma unroll
            for (int kk = 0; kk < 3; kk++) {
                #pragma unroll
                for (int c = 0; c < 8; c++) {
                    float w = w2sh[(fg * 8 + c) * 96 + f1 * 3 + kk];
                    #pragma unroll
                    for (int l = 0; l < 4; l++)
                        acc[c][l] = fmaf(a[l + kk], w, acc[c][l]);
                }
            }
        }
        #pragma unroll
        for (int c = 0; c < 8; c++) {
            int f2 = fg * 8 + c;
            float bb = b2sh[f2];
            float v0 = fmaxf(fmaxf(acc[c][0] + bb, 0.f), fmaxf(acc[c][1] + bb, 0.f));
            float v1 = fmaxf(fmaxf(acc[c][2] + bb, 0.f), fmaxf(acc[c][3] + bb, 0.f));
            y2sh[r * Y2S + f2 * 2 + 0] = v0;   // flatten order d = f2*2 + l
            y2sh[r * Y2S + f2 * 2 + 1] = v1;
        }
    }
    __syncthreads();

    // ---- load fc weights (overwrites conv2 weight region) ----
    {
        float* fcr = sm + OFF_W2;
        for (int i = tid; i < 8192; i += 256) {
            int j = i >> 7, d = i & 127;
            fcr[j * 129 + d] = f1wg[i];        // padded stride 129 (bank-safe)
        }
        if (tid < 64) fcr[8256 + tid] = f1bg[tid];
        for (int i = tid; i < 320; i += 256) fcr[8320 + i] = f2wg[i];
        if (tid < 5) fcr[8640 + tid] = f2bg[tid];
    }
    __syncthreads();

    // ---- fc1 + relu : 128 threads, thread tile 4 rows x 4 hidden ----
    if (tid < 128) {
        const float* fc1sh = sm + OFF_W2;
        const float* fb    = fc1sh + 8256;
        int rg = tid & 7;                      // rows rg*4..+3
        int hg = tid >> 3;                     // hidden hg*4..+3
        float acc[4][4];
        #pragma unroll
        for (int i = 0; i < 4; i++)
            #pragma unroll
            for (int j = 0; j < 4; j++) acc[i][j] = 0.f;

        #pragma unroll 4
        for (int d = 0; d < 128; d++) {
            float a0 = y2sh[(rg * 4 + 0) * Y2S + d];
            float a1 = y2sh[(rg * 4 + 1) * Y2S + d];
            float a2 = y2sh[(rg * 4 + 2) * Y2S + d];
            float a3 = y2sh[(rg * 4 + 3) * Y2S + d];
            float w0 = fc1sh[(hg * 4 + 0) * 129 + d];
            float w1 = fc1sh[(hg * 4 + 1) * 129 + d];
            float w2 = fc1sh[(hg * 4 + 2) * 129 + d];
            float w3 = fc1sh[(hg * 4 + 3) * 129 + d];
            acc[0][0] = fmaf(a0, w0, acc[0][0]); acc[0][1] = fmaf(a0, w1, acc[0][1]);
            acc[0][2] = fmaf(a0, w2, acc[0][2]); acc[0][3] = fmaf(a0, w3, acc[0][3]);
            acc[1][0] = fmaf(a1, w0, acc[1][0]); acc[1][1] = fmaf(a1, w1, acc[1][1]);
            acc[1][2] = fmaf(a1, w2, acc[1][2]); acc[1][3] = fmaf(a1, w3, acc[1][3]);
            acc[2][0] = fmaf(a2, w0, acc[2][0]); acc[2][1] = fmaf(a2, w1, acc[2][1]);
            acc[2][2] = fmaf(a2, w2, acc[2][2]); acc[2][3] = fmaf(a2, w3, acc[2][3]);
            acc[3][0] = fmaf(a3, w0, acc[3][0]); acc[3][1] = fmaf(a3, w1, acc[3][1]);
            acc[3][2] = fmaf(a3, w2, acc[3][2]); acc[3][3] = fmaf(a3, w3, acc[3][3]);
        }
        #pragma unroll
        for (int i = 0; i < 4; i++)
            #pragma unroll
            for (int j = 0; j < 4; j++)
                hsh[(rg * 4 + i) * HS + hg * 4 + j] =
                    fmaxf(acc[i][j] + fb[hg * 4 + j], 0.f);
    }
    __syncthreads();

    // ---- fc2 + transposed output write: out[b,t,o,n] ----
    if (tid < 160) {
        const float* fc2w = sm + OFF_W2 + 8320;
        const float* fc2b = sm + OFF_W2 + 8640;
        int r = tid & 31, o = tid >> 5;
        float acc = fc2b[o];
        #pragma unroll 8
        for (int j = 0; j < 64; j++)
            acc = fmaf(hsh[r * HS + j], fc2w[o * 64 + j], acc);
        int R  = row0 + r;
        int n  = R % NN;
        int bt = R / NN;
        out[((size_t)bt * 5 + o) * NN + n] = acc;
    }
}

// ---------------------------------------------------------------------------
extern "C" void kernel_launch(void* const* d_in, const int* in_sizes, int n_in,
                              void* d_out, int out_size)
{
    const float* x   = (const float*)d_in[0];
    const float* S   = (const float*)d_in[1];
    const float* w1  = (const float*)d_in[2];
    const float* b1  = (const float*)d_in[3];
    const float* w2  = (const float*)d_in[4];
    const float* b2  = (const float*)d_in[5];
    const float* f1w = (const float*)d_in[6];
    const float* f1b = (const float*)d_in[7];
    const float* f2w = (const float*)d_in[8];
    const float* f2b = (const float*)d_in[9];
    float* out = (float*)d_out;

    // 15 sequential diffusion steps (graph replay amortizes launch cost)
    for (int k = 1; k <= 15; k++)
        diffuse_step_kernel<<<BT, 128>>>(x, S, k);

    size_t smem = (size_t)SMEM_FLOATS * sizeof(float);
    cudaFuncSetAttribute(head_kernel,
                         cudaFuncAttributeMaxDynamicSharedMemorySize, (int)smem);
    head_kernel<<<(NB * NT * NN) / 32, 256, smem>>>(
        x, w1, b1, w2, b2, f1w, f1b, f2w, f2b, out);
}